// round 2
// baseline (speedup 1.0000x reference)
#include <cuda_runtime.h>
#include <cstdint>

// Segment mean over sorted residue_index (int32).
// atom_features: [N_ATOMS, 128] float32
// residue_index: [N_ATOMS] int32 (sorted ascending)
// out:           [N_RES, 128] float32  (sum / max(count,1))

#define N_RES 250000
#define THREADS 256

__device__ int g_starts[N_RES + 1];

// starts[q] = n_atoms default (handles all residues past the last atom)
__global__ void init_starts_kernel(int n_atoms)
{
    int q = blockIdx.x * blockDim.x + threadIdx.x;
    if (q <= N_RES) g_starts[q] = n_atoms;
}

// For each boundary i (ridx[i] != ridx[i-1]), fill starts[(prev, cur]] = i.
// i == 0 uses prev = -1, so starts[0..ridx[0]] = 0.
__global__ void build_starts_kernel(const int* __restrict__ ridx, int n_atoms)
{
    int i = blockIdx.x * blockDim.x + threadIdx.x;
    if (i >= n_atoms) return;
    int cur  = ridx[i];
    int prev = (i == 0) ? -1 : ridx[i - 1];
    for (int q = prev + 1; q <= cur; ++q)
        g_starts[q] = i;
}

// One warp per residue: coalesced float4 row sums.
__global__ void __launch_bounds__(THREADS)
residue_pool_kernel(const float4* __restrict__ feats,
                    float4* __restrict__ out)
{
    int warp_id = (blockIdx.x * THREADS + threadIdx.x) >> 5;
    int lane    = threadIdx.x & 31;
    if (warp_id >= N_RES) return;

    int start = g_starts[warp_id];
    int end   = g_starts[warp_id + 1];

    float4 acc = make_float4(0.f, 0.f, 0.f, 0.f);
    const float4* row = feats + (size_t)start * 32 + lane;
    for (int a = start; a < end; ++a, row += 32) {
        float4 v = __ldg(row);
        acc.x += v.x; acc.y += v.y; acc.z += v.z; acc.w += v.w;
    }

    int cnt = end - start;
    float inv = 1.0f / (float)(cnt > 0 ? cnt : 1);
    acc.x *= inv; acc.y *= inv; acc.z *= inv; acc.w *= inv;

    out[(size_t)warp_id * 32 + lane] = acc;
}

extern "C" void kernel_launch(void* const* d_in, const int* in_sizes, int n_in,
                              void* d_out, int out_size)
{
    const float4* feats = (const float4*)d_in[0];
    const int*    ridx  = (const int*)d_in[1];
    float4*       out   = (float4*)d_out;

    int n_atoms = in_sizes[1];

    init_starts_kernel<<<(N_RES + 1 + THREADS - 1) / THREADS, THREADS>>>(n_atoms);
    build_starts_kernel<<<(n_atoms + THREADS - 1) / THREADS, THREADS>>>(ridx, n_atoms);

    int total_threads = N_RES * 32;
    int blocks = (total_threads + THREADS - 1) / THREADS;
    residue_pool_kernel<<<blocks, THREADS>>>(feats, out);
}